// round 10
// baseline (speedup 1.0000x reference)
#include <cuda_runtime.h>
#include <cuda_fp16.h>
#include <cstdint>
#include <cstddef>

#define NTHREADS 256

#define FMA_F32X2(d, a, b, c) \
    asm("fma.rn.f32x2 %0, %1, %2, %3;" : "=l"(d) : "l"(a), "l"(b), "l"(c))
#define PACK2(d, lo, hi) \
    asm("mov.b64 %0, {%1, %2};" : "=l"(d) : "f"(lo), "f"(hi))
#define UNPACK2(lo, hi, s) \
    asm("mov.b64 {%0, %1}, %2;" : "=f"(lo), "=f"(hi) : "l"(s))

// ---------------------------------------------------------------------------
// 256 thr/CTA, 8-CTA cluster per batch. Whh in registers; P/W1h/GxT in smem.
// Sync = DSMEM mbarriers (no barrier.cluster in the time loop).
// LDS.128 quad checks (quad = (word>>2) mod 8, phase = 8 lanes):
//  - W1h half2 row 144, quarter offset 36q: quad = 4kk+q+i  -> bijective.
//  - GxT half2 row 72,  half offset 36p:    quad = 2r+p+i   -> bijective.
//  - WgtH half2 half offset 36p:            quad = p+i      -> 2 bcast addrs, ok.
//  - Hc 36-float chunks: Q quad = 2q+c2+2k.., gates quad = 4p+c4.. distinct.
//  - PEt [j][12]: float4 quad = 3j -> 8 consecutive j bijective.
//  - P fp32 stride 66, (j=tid>>1,q=tid&1) scalar: bank 2j+q+2i bijective.
// ---------------------------------------------------------------------------
struct __align__(16) Smem {
    float   P[128 * 66];        // 33792 B  [j][kk] x-part of energy L1 (+b1)
    __half2 W1h[64 * 144];      // 36864 B  [kk][h] (fp32 GEMM staging in prologue)
    __half2 GxT[128 * 72];      // 36864 B  [gate row][j] Wih_row . x_j
    float   Hc[2 * 288];        // double-buffered hidden, 36-float chunks
    float   PEt[128 * 12];      // [j][src_rank] partial energies (8 used)
    float   Qv[64];
    float   W2s[64];
    float   G[128];
    float   Bias[128];
    __half2 WgtH[80];           // softmax weights, halves at 36p
    unsigned long long mbPE;    // PE-exchange mbarrier (count 64)
    unsigned long long mbHC;    // h-gather mbarrier   (count 8)
};

__device__ __forceinline__ uint32_t s2u(const void* p) {
    uint32_t a;
    asm("{ .reg .u64 t; cvta.to.shared.u64 t, %1; cvt.u32.u64 %0, t; }"
        : "=r"(a) : "l"(p));
    return a;
}
__device__ __forceinline__ uint32_t mapa_rank(uint32_t addr, uint32_t rank) {
    uint32_t r;
    asm("mapa.shared::cluster.u32 %0, %1, %2;" : "=r"(r) : "r"(addr), "r"(rank));
    return r;
}
__device__ __forceinline__ void st_remote(uint32_t addr, float v) {
    asm volatile("st.shared::cluster.f32 [%0], %1;" :: "r"(addr), "f"(v) : "memory");
}
__device__ __forceinline__ void mbar_init(uint32_t addr, uint32_t count) {
    asm volatile("mbarrier.init.shared.b64 [%0], %1;" :: "r"(addr), "r"(count) : "memory");
}
__device__ __forceinline__ void mbar_arrive_remote(uint32_t raddr) {
    asm volatile("fence.acq_rel.cluster;\n\t"
                 "mbarrier.arrive.release.cluster.shared::cluster.b64 _, [%0];"
                 :: "r"(raddr) : "memory");
}
__device__ __forceinline__ int mbar_try(uint32_t addr, uint32_t parity) {
    uint32_t d;
    asm volatile("{\n\t.reg .pred p;\n\t"
        "mbarrier.try_wait.parity.acquire.cluster.shared::cta.b64 p, [%1], %2, 0x989680;\n\t"
        "selp.b32 %0, 1, 0, p;\n\t}"
        : "=r"(d) : "r"(addr), "r"(parity) : "memory");
    return (int)d;
}
__device__ __forceinline__ void mbar_wait(uint32_t addr, uint32_t parity) {
    while (!mbar_try(addr, parity)) {}
}
__device__ __forceinline__ void cluster_sync_once() {
    asm volatile("barrier.cluster.arrive.aligned;" ::: "memory");
    asm volatile("barrier.cluster.wait.aligned;" ::: "memory");
}
__device__ __forceinline__ float tanh_fast(float x) {   // MUFU, inner hdn only
    float y; asm("tanh.approx.f32 %0, %1;" : "=f"(y) : "f"(x)); return y;
}
__device__ __forceinline__ float tanh_acc(float x) {    // ~1e-6 err
    float e = __expf(2.f * x);
    return 1.f - __fdividef(2.f, e + 1.f);
}
__device__ __forceinline__ float sigm(float x) { return 1.f / (1.f + __expf(-x)); }

__global__ void __cluster_dims__(8, 1, 1) __launch_bounds__(NTHREADS, 1)
lstm_attn_kernel(const float* __restrict__ gx, const int* __restrict__ gseq,
                 const float* __restrict__ gW1, const float* __restrict__ gb1,
                 const float* __restrict__ gW2, const float* __restrict__ gb2,
                 const float* __restrict__ gWih, const float* __restrict__ gWhh,
                 const float* __restrict__ gbih, const float* __restrict__ gbhh,
                 float* __restrict__ out)
{
    extern __shared__ char smraw[];
    Smem& sm = *reinterpret_cast<Smem*>(smraw);
    const int tid = (int)threadIdx.x;
    const int b   = (int)blockIdx.x >> 3;   // batch = cluster id
    const int c   = (int)blockIdx.x & 7;    // rank within cluster
    const int len = gseq[b];
    const int lane = tid & 31;

    float* outO = out;                      // outputs  [8][128][256]
    float* outL = out + 262144;             // seq_lengths [8]
    float* outH = out + 262152;             // hidden   [1][8][256]
    float* outA = out + 264200;             // attn     [8][128][128]

    // ---------------- prologue ----------------
    for (int i = tid; i < 2 * 288; i += NTHREADS) sm.Hc[i] = 0.f;
    if (tid == 0) {
        mbar_init(s2u(&sm.mbPE), 64);
        mbar_init(s2u(&sm.mbHC), 8);
    }

    {   // zero padded output rows (d_out is poisoned)
        const int padT = 128 - len;
        for (int idx = (c << 8) + tid; idx < padT * 256; idx += 2048)
            outO[(size_t)b * 32768 + (size_t)len * 256 + idx] = 0.f;
        for (int idx = (c << 8) + tid; idx < padT * 128; idx += 2048)
            outA[(size_t)b * 16384 + (size_t)len * 128 + idx] = 0.f;
        if (c == 0 && tid == 0) outL[b] = (float)len;
    }

    // Unified prologue GEMM: 192 W-rows (64 -> P slice, 128 -> GxT) x 128 j.
    // thread = (jq = tid>>2, qq = tid&3 e-quarter); f32x2 packed math.
    {
        const int jq = tid >> 2;
        const int qq = tid & 3;
        float* wst = reinterpret_cast<float*>(sm.W1h);  // 16 x 272 fp32 staging

        for (int pass = 0; pass < 12; ++pass) {
            __syncthreads();                 // prior-pass wst reads complete
            for (int i = tid; i < 16 * 256; i += NTHREADS) {
                int r = i >> 8, e = i & 255;
                int row = pass * 16 + r;
                float v;
                if (row < 64) {
                    v = gW1[(size_t)(c * 64 + row) * 512 + e];
                } else {
                    int idx = row - 64, g = idx >> 5, u = idx & 31;
                    v = gWih[(size_t)(g * 256 + c * 32 + u) * 256 + e];
                }
                wst[r * 272 + (e >> 6) * 68 + (e & 63)] = v;
            }
            __syncthreads();

            for (int jb = 0; jb < 2; ++jb) {
                const int j = jb * 64 + jq;
                unsigned long long xp[32];
                const float* xrow = gx + (size_t)b * 32768 + (size_t)j * 256 + qq * 64;
                #pragma unroll
                for (int i = 0; i < 16; ++i) {
                    ulonglong2 v = *reinterpret_cast<const ulonglong2*>(xrow + 4 * i);
                    xp[2 * i] = v.x; xp[2 * i + 1] = v.y;
                }
                #pragma unroll 2
                for (int r = 0; r < 16; ++r) {
                    const ulonglong2* wr =
                        reinterpret_cast<const ulonglong2*>(wst + r * 272 + qq * 68);
                    unsigned long long acc0, acc1;
                    PACK2(acc0, 0.f, 0.f);
                    PACK2(acc1, 0.f, 0.f);
                    #pragma unroll
                    for (int i = 0; i < 16; ++i) {
                        ulonglong2 w = wr[i];
                        FMA_F32X2(acc0, xp[2 * i],     w.x, acc0);
                        FMA_F32X2(acc1, xp[2 * i + 1], w.y, acc1);
                    }
                    float l0, h0, l1, h1;
                    UNPACK2(l0, h0, acc0);
                    UNPACK2(l1, h1, acc1);
                    float s = (l0 + h0) + (l1 + h1);
                    s += __shfl_xor_sync(0xffffffffu, s, 1);
                    s += __shfl_xor_sync(0xffffffffu, s, 2);
                    if (qq == 0) {
                        int row = pass * 16 + r;
                        if (row < 64) {
                            sm.P[j * 66 + row] = s + gb1[c * 64 + row];
                        } else {
                            int idx = row - 64;
                            reinterpret_cast<__half*>(sm.GxT)
                                [idx * 144 + (j >> 6) * 72 + (j & 63)] = __float2half_rn(s);
                        }
                    }
                }
            }
        }
        __syncthreads();                     // last-pass wst reads complete
    }

    // W1h fp16 (overwrites its own staging area). pair m -> [kk*144 + (m>>5)*36 + (m&31)]
    for (int i = tid; i < 64 * 128; i += NTHREADS) {
        int kk = i >> 7, m = i & 127;
        float2 v = *reinterpret_cast<const float2*>(
            gW1 + (size_t)(c * 64 + kk) * 512 + 256 + 2 * m);
        sm.W1h[kk * 144 + (m >> 5) * 36 + (m & 31)] = __floats2half2_rn(v.x, v.y);
    }
    if (tid < 64) sm.W2s[tid] = gW2[c * 64 + tid];
    if (tid < 128) {
        int g = tid >> 5, uu = tid & 31;
        sm.Bias[tid] = gbih[g * 256 + c * 32 + uu] + gbhh[g * 256 + c * 32 + uu];
    }

    // ---- Whh gate weights into REGISTERS: row r = tid>>1, half p = tid&1 ----
    const int r_row = tid >> 1, p = tid & 1;
    uint32_t whh_r[64];
    {
        const int grow = (r_row >> 5) * 256 + c * 32 + (r_row & 31);
        const float* bhh_ = gWhh + (size_t)grow * 256 + (p << 7);
        #pragma unroll
        for (int i = 0; i < 64; ++i) {
            float2 v = *reinterpret_cast<const float2*>(bhh_ + 2 * i);
            __half2 h2 = __floats2half2_rn(v.x, v.y);
            whh_r[i] = *reinterpret_cast<uint32_t*>(&h2);
        }
    }
    __syncthreads();
    cluster_sync_once();    // mbarriers + all smem visible cluster-wide

    // hoisted remote addresses
    uint32_t peR[8], hcR[8];
    {
        uint32_t peA = s2u(sm.PEt), hcA = s2u(sm.Hc);
        #pragma unroll
        for (int rr = 0; rr < 8; ++rr) {
            peR[rr] = mapa_rank(peA, rr);
            hcR[rr] = mapa_rank(hcA, rr);
        }
    }
    const uint32_t peArr = mapa_rank(s2u(&sm.mbPE), (uint32_t)(lane & 7));
    const uint32_t hcArr = mapa_rank(s2u(&sm.mbHC), (uint32_t)(lane & 7));
    const uint32_t mbPEl = s2u(&sm.mbPE);
    const uint32_t mbHCl = s2u(&sm.mbHC);

    const float b2v = gb2[0];
    float creg = 0.f, hlast = 0.f;          // per-unit state (threads 0..31)

    // ---------------- time loop ----------------
    for (int t = 0; t < len; ++t) {
        if (t) mbar_wait(mbHCl, (t + 1) & 1);   // h(t) gathered everywhere
        const float* Hcur = sm.Hc + (t & 1) * 288;

        // ---- Q[kk] = h . W1h[kk,:]   (kk = tid>>2, q = tid&3) ----
        {
            const int kk = tid >> 2, q = tid & 3;
            const float4* wr4 = reinterpret_cast<const float4*>(sm.W1h + kk * 144 + q * 36);
            float a0 = 0.f, a1 = 0.f;
            #pragma unroll
            for (int c2 = 0; c2 < 2; ++c2) {
                const float* hch = Hcur + (2 * q + c2) * 36;
                #pragma unroll
                for (int k = 0; k < 4; ++k) {
                    float4 wv = wr4[c2 * 4 + k];
                    float4 h0 = *reinterpret_cast<const float4*>(hch + 8 * k);
                    float4 h1 = *reinterpret_cast<const float4*>(hch + 8 * k + 4);
                    float2 w0 = __half22float2(*reinterpret_cast<const __half2*>(&wv.x));
                    float2 w1 = __half22float2(*reinterpret_cast<const __half2*>(&wv.y));
                    float2 w2 = __half22float2(*reinterpret_cast<const __half2*>(&wv.z));
                    float2 w3 = __half22float2(*reinterpret_cast<const __half2*>(&wv.w));
                    a0 = fmaf(w0.x, h0.x, a0); a1 = fmaf(w0.y, h0.y, a1);
                    a0 = fmaf(w1.x, h0.z, a0); a1 = fmaf(w1.y, h0.w, a1);
                    a0 = fmaf(w2.x, h1.x, a0); a1 = fmaf(w2.y, h1.y, a1);
                    a0 = fmaf(w3.x, h1.z, a0); a1 = fmaf(w3.y, h1.w, a1);
                }
            }
            float acc = a0 + a1;
            acc += __shfl_xor_sync(0xffffffffu, acc, 1);
            acc += __shfl_xor_sync(0xffffffffu, acc, 2);
            if (q == 0) sm.Qv[kk] = acc;
        }
        __syncthreads();

        // ---- partial energies: pe[j] = sum_kk tanh(P+Q)*W2 (j=tid>>1,q=tid&1) ----
        {
            const int j = tid >> 1, q = tid & 1;
            float acc = 0.f;
            #pragma unroll
            for (int i = 0; i < 32; ++i) {
                int kk = q + 2 * i;
                float v = sm.P[j * 66 + kk] + sm.Qv[kk];
                acc = fmaf(tanh_fast(v), sm.W2s[kk], acc);
            }
            acc += __shfl_xor_sync(0xffffffffu, acc, 1);
            if (q == 0) {
                uint32_t off = (uint32_t)((j * 12 + c) * 4);
                #pragma unroll
                for (int rr = 0; rr < 8; ++rr) st_remote(peR[rr] + off, acc);
            }
        }
        __syncwarp();
        if (lane < 8) mbar_arrive_remote(peArr);   // 8 warps x 8 ranks = 64 arrivals

        // ---- hidden behind PE exchange: Whh half of the gates ----
        float a_hh;
        {
            float a0 = 0.f, a1 = 0.f, a2 = 0.f, a3 = 0.f;
            #pragma unroll
            for (int c4 = 0; c4 < 4; ++c4) {
                const float* hch = Hcur + (4 * p + c4) * 36;
                #pragma unroll
                for (int k = 0; k < 4; ++k) {
                    float4 h0 = *reinterpret_cast<const float4*>(hch + 8 * k);
                    float4 h1 = *reinterpret_cast<const float4*>(hch + 8 * k + 4);
                    float2 w0 = __half22float2(
                        *reinterpret_cast<const __half2*>(&whh_r[c4 * 16 + 4 * k]));
                    float2 w1 = __half22float2(
                        *reinterpret_cast<const __half2*>(&whh_r[c4 * 16 + 4 * k + 1]));
                    float2 w2 = __half22float2(
                        *reinterpret_cast<const __half2*>(&whh_r[c4 * 16 + 4 * k + 2]));
                    float2 w3 = __half22float2(
                        *reinterpret_cast<const __half2*>(&whh_r[c4 * 16 + 4 * k + 3]));
                    a0 = fmaf(w0.x, h0.x, a0); a1 = fmaf(w0.y, h0.y, a1);
                    a2 = fmaf(w1.x, h0.z, a2); a3 = fmaf(w1.y, h0.w, a3);
                    a0 = fmaf(w2.x, h1.x, a0); a1 = fmaf(w2.y, h1.y, a1);
                    a2 = fmaf(w3.x, h1.z, a2); a3 = fmaf(w3.y, h1.w, a3);
                }
            }
            a_hh = (a0 + a1) + (a2 + a3);
        }
        mbar_wait(mbPEl, t & 1);               // PE ready everywhere

        // ---- warp-local softmax (all 128 j per warp; tanh-bounded, no max) ----
        {
            float w[4];
            float ssum = 0.f;
            #pragma unroll
            for (int qd = 0; qd < 4; ++qd) {
                const int j = lane + 32 * qd;
                const float4* pej = reinterpret_cast<const float4*>(sm.PEt + j * 12);
                float4 u0 = pej[0], u1 = pej[1];
                float s = ((u0.x + u0.y) + (u0.z + u0.w)) +
                          ((u1.x + u1.y) + (u1.z + u1.w));
                float e = (j < len) ? tanh_acc(s + b2v) : -1e30f;
                w[qd] = __expf(e);
                ssum += w[qd];
            }
            #pragma unroll
            for (int o = 16; o; o >>= 1) ssum += __shfl_xor_sync(0xffffffffu, ssum, o);
            const float inv = __fdividef(1.f, ssum);
            #pragma unroll
            for (int qd = 0; qd < 4; ++qd) {
                w[qd] *= inv;
                float hi = __shfl_down_sync(0xffffffffu, w[qd], 1);
                if (!(lane & 1))
                    sm.WgtH[36 * (qd >> 1) + 16 * (qd & 1) + (lane >> 1)] =
                        __floats2half2_rn(w[qd], hi);
            }
            if (c == 0 && tid < 32) {
                float* row = outA + (size_t)(b * 128 + t) * 128;
                #pragma unroll
                for (int qd = 0; qd < 4; ++qd) row[lane + 32 * qd] = w[qd];
            }
        }
        __syncwarp();

        // ---- gates: a_hh + sum_j w_j * Gx[row][j]  (half p of j) ----
        {
            float a0 = a_hh, a1 = 0.f;
            const float4* gx4 = reinterpret_cast<const float4*>(sm.GxT + r_row * 72 + 36 * p);
            const float4* wv4 = reinterpret_cast<const float4*>(sm.WgtH + 36 * p);
            #pragma unroll
            for (int i2 = 0; i2 < 8; ++i2) {
                float4 g4 = gx4[i2];
                float4 w4 = wv4[i2];
                float2 g0 = __half22float2(*reinterpret_cast<const __half2*>(&g4.x));
                float2 g1 = __half22float2(*reinterpret_cast<const __half2*>(&g4.y));
                float2 g2 = __half22float2(*reinterpret_cast<const __half2*>(&g4.z));
                float2 g3 = __half22float2(*reinterpret_cast<const __half2*>(&g4.w));
                float2 q0 = __half22float2(*reinterpret_cast<const __half2*>(&w4.x));
                float2 q1 = __half22float2(*reinterpret_cast<const __half2*>(&w4.y));
                float2 q2 = __half22float2(*reinterpret_cast<const __half2*>(&w4.z));
                float2 q3 = __half22float2(*reinterpret_cast<const __half2*>(&w4.w));
                a0 = fmaf(q0.x, g0.x, a0); a1 = fmaf(q0.y, g0.y, a1);
                a0 = fmaf(q1.x, g1.x, a0); a1 = fmaf(q1.y, g1.y, a1);
                a0 = fmaf(q2.x, g2.x, a0); a1 = fmaf(q2.y, g2.y, a1);
                a0 = fmaf(q3.x, g3.x, a0); a1 = fmaf(q3.y, g3.y, a1);
            }
            float acc = a0 + a1;
            acc += __shfl_xor_sync(0xffffffffu, acc, 1);
            if (p == 0) sm.G[r_row] = acc + sm.Bias[r_row];
        }
        __syncthreads();

        // ---- state update + h scatter straight from registers (warp 0) ----
        if (tid < 32) {
            float gi = sm.G[tid],      gf = sm.G[32 + tid];
            float gg = sm.G[64 + tid], go = sm.G[96 + tid];
            creg = sigm(gf) * creg + sigm(gi) * tanh_acc(gg);
            float hn = sigm(go) * tanh_acc(creg);
            if (t == len - 1) hlast = hn;
            outO[(size_t)(b * 128 + t) * 256 + (c * 32 + tid)] = hn;
            uint32_t off = (uint32_t)(((((t + 1) & 1) * 288) + c * 36 + tid) * 4);
            #pragma unroll
            for (int rr = 0; rr < 8; ++rr) st_remote(hcR[rr] + off, hn);
            __syncwarp(0xffffffffu);
            if (tid < 8) mbar_arrive_remote(hcArr);   // 8 ranks x 1 = 8 arrivals
        }
    }

    cluster_sync_once();    // keep peer smem alive until all exchanges land
    if (tid < 32)
        outH[(size_t)b * 256 + c * 32 + tid] = hlast;
}

extern "C" void kernel_launch(void* const* d_in, const int* in_sizes, int n_in,
                              void* d_out, int out_size) {
    (void)in_sizes; (void)n_in; (void)out_size;
    const float* x    = (const float*)d_in[0];
    const int*   seq  = (const int*)d_in[1];
    const float* W1   = (const float*)d_in[2];
    const float* b1   = (const float*)d_in[3];
    const float* W2   = (const float*)d_in[4];
    const float* b2   = (const float*)d_in[5];
    const float* Wih  = (const float*)d_in[6];
    const float* Whh  = (const float*)d_in[7];
    const float* bih  = (const float*)d_in[8];
    const float* bhh  = (const float*)d_in[9];
    float* out = (float*)d_out;

    cudaFuncSetAttribute(lstm_attn_kernel,
                         cudaFuncAttributeMaxDynamicSharedMemorySize,
                         (int)sizeof(Smem));
    lstm_attn_kernel<<<64, NTHREADS, sizeof(Smem)>>>(
        x, seq, W1, b1, W2, b2, Wih, Whh, bih, bhh, out);
}